// round 1
// baseline (speedup 1.0000x reference)
#include <cuda_runtime.h>

#define T_SEQ 2048
#define I_IN 7
#define H_DIM 64
#define G_DIM 256   // 4*H
#define B_SZ 256
#define O_DIM 3

using u64 = unsigned long long;

// ---------- packed f32x2 helpers (Blackwell FFMA2 path) ----------
__device__ __forceinline__ u64 pack2(float lo, float hi) {
    u64 r;
    asm("mov.b64 %0, {%1, %2};" : "=l"(r) : "f"(lo), "f"(hi));
    return r;
}
__device__ __forceinline__ void unpack2(u64 v, float& lo, float& hi) {
    asm("mov.b64 {%0, %1}, %2;" : "=f"(lo), "=f"(hi) : "l"(v));
}
__device__ __forceinline__ void ffma2(u64& acc, u64 a, u64 b) {
    asm("fma.rn.f32x2 %0, %1, %2, %0;" : "+l"(acc) : "l"(a), "l"(b));
}

// ---------- activations (MUFU.EX2/RCP based, ~2^-22 accurate) ----------
__device__ __forceinline__ float sigm(float x) {
    return __fdividef(1.0f, 1.0f + __expf(-x));
}
__device__ __forceinline__ float tanh_acc(float x) {
    // 1 - 2/(exp(2x)+1); exact limits at +/-inf
    return 1.0f - __fdividef(2.0f, __expf(2.0f * x) + 1.0f);
}

// Forward final hidden state, written by kernel1 and read by kernel2.
__device__ float g_hF[B_SZ * H_DIM];

// ---------- shared memory layout (dynamic) ----------
struct Smem {
    float2 xs[T_SEQ][8];       // xs[t][i] = {x[b0,t,i], x[b1,t,i]}, i<7 valid, [7] zero pad. 131072 B
    float  hs[2][H_DIM];       // h state per batch elem.                                      512 B
    float2 zs[G_DIM];          // zs[g] = {z_b0[g], z_b1[g]}                                  2048 B
};                             // total 133632 B

// input projection + bias for timestep t, packed across the batch pair
__device__ __forceinline__ u64 input_proj(const Smem& s, int t, const u64* Wi, u64 biasp) {
    u64 acc = biasp;
    const ulonglong2* xp = reinterpret_cast<const ulonglong2*>(s.xs[t]);
#pragma unroll
    for (int q = 0; q < 4; q++) {
        ulonglong2 v = xp[q];               // two {b0,b1} pairs per 16B load
        ffma2(acc, Wi[2 * q], v.x);
        ffma2(acc, Wi[2 * q + 1], v.y);     // q==3,second pair: Wi[7]=0, pad=0 -> no-op
    }
    return acc;
}

__global__ void __launch_bounds__(256, 1)
lstm_fwd_kernel(const float* __restrict__ x,
                const float* __restrict__ W_ih,
                const float* __restrict__ W_hh,
                const float* __restrict__ b_ih,
                const float* __restrict__ b_hh) {
    extern __shared__ Smem sh[];
    Smem& s = sh[0];

    const int tid = threadIdx.x;
    const int b0 = blockIdx.x * 2;

    // ---- stage x for both batch elements into smem, interleaved as pairs ----
    {
        const float* x0 = x + (size_t)b0 * T_SEQ * I_IN;
        const float* x1 = x + (size_t)(b0 + 1) * T_SEQ * I_IN;
        for (int idx = tid; idx < T_SEQ * I_IN; idx += 256) {
            int t = idx / I_IN;
            int i = idx - t * I_IN;
            s.xs[t][i] = make_float2(x0[idx], x1[idx]);
        }
        for (int t = tid; t < T_SEQ; t += 256) s.xs[t][7] = make_float2(0.f, 0.f);
        if (tid < 2 * H_DIM) ((float*)s.hs)[tid] = 0.f;
    }

    // ---- per-thread weights in registers ----
    const int g = tid;   // gate-output index 0..255
    u64 Wk[32];          // W_hh[g, :] packed along k
    {
        const ulonglong2* wp = reinterpret_cast<const ulonglong2*>(W_hh + g * H_DIM);
#pragma unroll
        for (int q = 0; q < 16; q++) {
            ulonglong2 v = wp[q];
            Wk[2 * q] = v.x;
            Wk[2 * q + 1] = v.y;
        }
    }
    u64 Wi[8];           // W_ih[g, i] duplicated into both lanes (batch packing)
#pragma unroll
    for (int i = 0; i < 7; i++) {
        float w = W_ih[g * I_IN + i];
        Wi[i] = pack2(w, w);
    }
    Wi[7] = 0ull;
    const float bias = b_ih[g] + b_hh[g];
    const u64 biasp = pack2(bias, bias);

    // combiner assignment: tid<128 -> (batch cb, hidden unit cj)
    const int cb = tid >> 6;
    const int cj = tid & 63;
    float c_state = 0.f;

    __syncthreads();

    u64 accX = input_proj(s, 0, Wi, biasp);   // t=0 input part

    for (int t = 0; t < T_SEQ; t++) {
        // ---- recurrent part: z += W_hh[g,:] . h  (f32x2 packed along k) ----
        u64 a0 = 0ull, a1 = 0ull;
        const ulonglong2* h0p = reinterpret_cast<const ulonglong2*>(s.hs[0]);
        const ulonglong2* h1p = reinterpret_cast<const ulonglong2*>(s.hs[1]);
#pragma unroll
        for (int q = 0; q < 16; q++) {
            ulonglong2 v0 = h0p[q];
            ffma2(a0, Wk[2 * q], v0.x);
            ffma2(a0, Wk[2 * q + 1], v0.y);
            ulonglong2 v1 = h1p[q];
            ffma2(a1, Wk[2 * q], v1.x);
            ffma2(a1, Wk[2 * q + 1], v1.y);
        }
        float xl, xh, a0l, a0h, a1l, a1h;
        unpack2(accX, xl, xh);
        unpack2(a0, a0l, a0h);
        unpack2(a1, a1l, a1h);
        s.zs[g] = make_float2(xl + a0l + a0h, xh + a1l + a1h);

        __syncthreads();

        // ---- gate combine (threads 0..127), overlapped with next input proj ----
        if (tid < 2 * H_DIM) {
            const float* zf = reinterpret_cast<const float*>(s.zs);
            float zi = zf[2 * cj + cb];
            float zff = zf[2 * (H_DIM + cj) + cb];
            float zg = zf[2 * (2 * H_DIM + cj) + cb];
            float zo = zf[2 * (3 * H_DIM + cj) + cb];
            float ig = sigm(zi);
            float fg = sigm(zff);
            float gg = tanh_acc(zg);
            float og = sigm(zo);
            c_state = fg * c_state + ig * gg;
            s.hs[cb][cj] = og * tanh_acc(c_state);
        }
        if (t + 1 < T_SEQ) accX = input_proj(s, t + 1, Wi, biasp);

        __syncthreads();
    }

    if (tid < 2 * H_DIM) g_hF[(b0 + cb) * H_DIM + cj] = s.hs[cb][cj];
}

// One backward LSTM step (from zero state on x[:,T-1,:]) + final linear.
__global__ void __launch_bounds__(256)
lstm_bwd_out_kernel(const float* __restrict__ x,
                    const float* __restrict__ W_ih_b,
                    const float* __restrict__ b_ih_b,
                    const float* __restrict__ b_hh_b,
                    const float* __restrict__ W_lin,
                    const float* __restrict__ b_lin,
                    float* __restrict__ out) {
    __shared__ float zs[G_DIM];
    __shared__ float hb[H_DIM];
    const int b = blockIdx.x;
    const int g = threadIdx.x;

    const float* xt = x + ((size_t)b * T_SEQ + (T_SEQ - 1)) * I_IN;
    float z = b_ih_b[g] + b_hh_b[g];
#pragma unroll
    for (int i = 0; i < I_IN; i++) z += W_ih_b[g * I_IN + i] * xt[i];
    zs[g] = z;
    __syncthreads();

    if (g < H_DIM) {
        float ig = sigm(zs[g]);
        float gg = tanh_acc(zs[2 * H_DIM + g]);
        float og = sigm(zs[3 * H_DIM + g]);
        float c = ig * gg;              // f * c_prev = 0 at first step
        hb[g] = og * tanh_acc(c);
    }
    __syncthreads();

    if (g < O_DIM) {
        float acc = b_lin[g];
        const float* wrow = W_lin + g * (2 * H_DIM);
        const float* hf = g_hF + b * H_DIM;
#pragma unroll 8
        for (int j = 0; j < H_DIM; j++) acc += wrow[j] * hf[j];
#pragma unroll 8
        for (int j = 0; j < H_DIM; j++) acc += wrow[H_DIM + j] * hb[j];
        out[b * O_DIM + g] = acc;
    }
}

extern "C" void kernel_launch(void* const* d_in, const int* in_sizes, int n_in,
                              void* d_out, int out_size) {
    const float* x      = (const float*)d_in[0];
    const float* Wih_f  = (const float*)d_in[1];
    const float* Whh_f  = (const float*)d_in[2];
    const float* bih_f  = (const float*)d_in[3];
    const float* bhh_f  = (const float*)d_in[4];
    const float* Wih_b  = (const float*)d_in[5];
    const float* bih_b  = (const float*)d_in[7];
    const float* bhh_b  = (const float*)d_in[8];
    const float* Wlin   = (const float*)d_in[9];
    const float* blin   = (const float*)d_in[10];
    float* out = (float*)d_out;

    cudaFuncSetAttribute(lstm_fwd_kernel,
                         cudaFuncAttributeMaxDynamicSharedMemorySize,
                         (int)sizeof(Smem));

    lstm_fwd_kernel<<<B_SZ / 2, 256, sizeof(Smem)>>>(x, Wih_f, Whh_f, bih_f, bhh_f);
    lstm_bwd_out_kernel<<<B_SZ, 256>>>(x, Wih_b, bih_b, bhh_b, Wlin, blin, out);
}

// round 2
// speedup vs baseline: 1.1081x; 1.1081x over previous
#include <cuda_runtime.h>

#define T_SEQ 2048
#define I_IN 7
#define H_DIM 64
#define G_DIM 256   // 4*H
#define B_SZ 256
#define O_DIM 3

using u64 = unsigned long long;

// ---------- packed f32x2 helpers (Blackwell FFMA2 path) ----------
__device__ __forceinline__ u64 pack2(float lo, float hi) {
    u64 r;
    asm("mov.b64 %0, {%1, %2};" : "=l"(r) : "f"(lo), "f"(hi));
    return r;
}
__device__ __forceinline__ void unpack2(u64 v, float& lo, float& hi) {
    asm("mov.b64 {%0, %1}, %2;" : "=f"(lo), "=f"(hi) : "l"(v));
}
__device__ __forceinline__ void ffma2(u64& acc, u64 a, u64 b) {
    asm("fma.rn.f32x2 %0, %1, %2, %0;" : "+l"(acc) : "l"(a), "l"(b));
}

// ---------- activations (MUFU.EX2/RCP based, ~2^-22 accurate) ----------
__device__ __forceinline__ float sigm(float x) {
    return __fdividef(1.0f, 1.0f + __expf(-x));
}
__device__ __forceinline__ float tanh_acc(float x) {
    return 1.0f - __fdividef(2.0f, __expf(2.0f * x) + 1.0f);
}

// Forward final hidden state, written by kernel1 and read by kernel2.
__device__ float g_hF[B_SZ * H_DIM];

// ---------- shared memory layout (dynamic), one batch element per CTA ----------
struct Smem {
    float xs[T_SEQ][8];    // xs[t][i], i<7 valid, [7] zero pad.  65536 B
    float hs[H_DIM];       // h state.                              256 B (16B-aligned)
    float zs[G_DIM];       // pre-activation gates.                1024 B
};                         // total 66816 B -> 2 CTAs/SM = 133632 B

__global__ void __launch_bounds__(256, 2)
lstm_fwd_kernel(const float* __restrict__ x,
                const float* __restrict__ W_ih,
                const float* __restrict__ W_hh,
                const float* __restrict__ b_ih,
                const float* __restrict__ b_hh) {
    extern __shared__ Smem sh[];
    Smem& s = sh[0];

    const int tid = threadIdx.x;
    const int b = blockIdx.x;

    // ---- stage this batch element's x into smem ----
    {
        const float* xb = x + (size_t)b * T_SEQ * I_IN;
        for (int idx = tid; idx < T_SEQ * I_IN; idx += 256) {
            int t = idx / I_IN;
            int i = idx - t * I_IN;
            s.xs[t][i] = xb[idx];
        }
        for (int t = tid; t < T_SEQ; t += 256) s.xs[t][7] = 0.f;
        if (tid < H_DIM) s.hs[tid] = 0.f;
    }

    // ---- per-thread weights in registers (thread g owns gate-output g) ----
    const int g = tid;
    u64 Wk[32];   // W_hh[g,:] packed along k as f32x2 pairs
    {
        const ulonglong2* wp = reinterpret_cast<const ulonglong2*>(W_hh + g * H_DIM);
#pragma unroll
        for (int q = 0; q < 16; q++) {
            ulonglong2 v = wp[q];
            Wk[2 * q] = v.x;
            Wk[2 * q + 1] = v.y;
        }
    }
    u64 Wi[4];    // W_ih[g,:] packed along i (pad i=7 with 0)
    {
        float w[8];
#pragma unroll
        for (int i = 0; i < 7; i++) w[i] = W_ih[g * I_IN + i];
        w[7] = 0.f;
#pragma unroll
        for (int q = 0; q < 4; q++) Wi[q] = pack2(w[2 * q], w[2 * q + 1]);
    }
    const float bias = b_ih[g] + b_hh[g];
    float c_state = 0.f;

    __syncthreads();

    // input projection for timestep t (packed along i)
    auto iproj = [&](int t) -> float {
        u64 acc = 0ull;
        const ulonglong2* xp = reinterpret_cast<const ulonglong2*>(s.xs[t]);
        ulonglong2 v0 = xp[0], v1 = xp[1];
        ffma2(acc, Wi[0], v0.x);
        ffma2(acc, Wi[1], v0.y);
        ffma2(acc, Wi[2], v1.x);
        ffma2(acc, Wi[3], v1.y);
        float lo, hi;
        unpack2(acc, lo, hi);
        return lo + hi;
    };

    float accX = iproj(0) + bias;

    for (int t = 0; t < T_SEQ; t++) {
        // ---- recurrent dot: z_g = accX + W_hh[g,:] . h  (2 accumulators for ILP) ----
        u64 a0 = 0ull, a1 = 0ull;
        const ulonglong2* hp = reinterpret_cast<const ulonglong2*>(s.hs);
#pragma unroll
        for (int q = 0; q < 8; q++) {
            ulonglong2 v0 = hp[2 * q];
            ffma2(a0, Wk[4 * q], v0.x);
            ffma2(a0, Wk[4 * q + 1], v0.y);
            ulonglong2 v1 = hp[2 * q + 1];
            ffma2(a1, Wk[4 * q + 2], v1.x);
            ffma2(a1, Wk[4 * q + 3], v1.y);
        }
        float l0, h0, l1, h1;
        unpack2(a0, l0, h0);
        unpack2(a1, l1, h1);
        s.zs[g] = accX + ((l0 + h0) + (l1 + h1));

        __syncthreads();

        // ---- gate combine (threads 0..63), overlapped with next input proj ----
        if (tid < H_DIM) {
            float zi = s.zs[tid];
            float zf = s.zs[H_DIM + tid];
            float zg = s.zs[2 * H_DIM + tid];
            float zo = s.zs[3 * H_DIM + tid];
            float ig = sigm(zi);
            float fg = sigm(zf);
            float gg = tanh_acc(zg);
            float og = sigm(zo);
            c_state = fg * c_state + ig * gg;
            s.hs[tid] = og * tanh_acc(c_state);
        }
        if (t + 1 < T_SEQ) accX = iproj(t + 1) + bias;

        __syncthreads();
    }

    if (tid < H_DIM) g_hF[b * H_DIM + tid] = s.hs[tid];
}

// One backward LSTM step (from zero state on x[:,T-1,:]) + final linear.
__global__ void __launch_bounds__(256)
lstm_bwd_out_kernel(const float* __restrict__ x,
                    const float* __restrict__ W_ih_b,
                    const float* __restrict__ b_ih_b,
                    const float* __restrict__ b_hh_b,
                    const float* __restrict__ W_lin,
                    const float* __restrict__ b_lin,
                    float* __restrict__ out) {
    __shared__ float zs[G_DIM];
    __shared__ float hb[H_DIM];
    const int b = blockIdx.x;
    const int g = threadIdx.x;

    const float* xt = x + ((size_t)b * T_SEQ + (T_SEQ - 1)) * I_IN;
    float z = b_ih_b[g] + b_hh_b[g];
#pragma unroll
    for (int i = 0; i < I_IN; i++) z += W_ih_b[g * I_IN + i] * xt[i];
    zs[g] = z;
    __syncthreads();

    if (g < H_DIM) {
        float ig = sigm(zs[g]);
        float gg = tanh_acc(zs[2 * H_DIM + g]);
        float og = sigm(zs[3 * H_DIM + g]);
        float c = ig * gg;              // f * c_prev = 0 at first step
        hb[g] = og * tanh_acc(c);
    }
    __syncthreads();

    if (g < O_DIM) {
        float acc = b_lin[g];
        const float* wrow = W_lin + g * (2 * H_DIM);
        const float* hf = g_hF + b * H_DIM;
#pragma unroll 8
        for (int j = 0; j < H_DIM; j++) acc += wrow[j] * hf[j];
#pragma unroll 8
        for (int j = 0; j < H_DIM; j++) acc += wrow[H_DIM + j] * hb[j];
        out[b * O_DIM + g] = acc;
    }
}

extern "C" void kernel_launch(void* const* d_in, const int* in_sizes, int n_in,
                              void* d_out, int out_size) {
    const float* x      = (const float*)d_in[0];
    const float* Wih_f  = (const float*)d_in[1];
    const float* Whh_f  = (const float*)d_in[2];
    const float* bih_f  = (const float*)d_in[3];
    const float* bhh_f  = (const float*)d_in[4];
    const float* Wih_b  = (const float*)d_in[5];
    const float* bih_b  = (const float*)d_in[7];
    const float* bhh_b  = (const float*)d_in[8];
    const float* Wlin   = (const float*)d_in[9];
    const float* blin   = (const float*)d_in[10];
    float* out = (float*)d_out;

    cudaFuncSetAttribute(lstm_fwd_kernel,
                         cudaFuncAttributeMaxDynamicSharedMemorySize,
                         (int)sizeof(Smem));

    lstm_fwd_kernel<<<B_SZ, 256, sizeof(Smem)>>>(x, Wih_f, Whh_f, bih_f, bhh_f);
    lstm_bwd_out_kernel<<<B_SZ, 256>>>(x, Wih_b, bih_b, bhh_b, Wlin, blin, out);
}